// round 2
// baseline (speedup 1.0000x reference)
#include <cuda_runtime.h>
#include <math.h>

#define B_ 8
#define S_ 1024
#define C_ 768
#define H_ 12
#define D_ 64
#define M_ (B_*S_)
#define K_ C_

// Scratch (allocation-free contract: __device__ globals)
__device__ float g_q[B_*H_*S_*D_];   // [B,H,S,D]
__device__ float g_k[B_*H_*S_*D_];
__device__ float g_v[B_*H_*S_*D_];
__device__ float g_y[M_*C_];         // attention output in [B,S,C]

// ============================================================
// SGEMM: out[m,n] = sum_k A[m,k] * W[n,k] + bias[n]
// A is [M,K] row-major, W is [N,K] row-major (both K-contiguous -> "NT")
// BM=BN=128, BK=8, 256 threads, 8x8 accum per thread (quadrant layout)
// MODE 0: A = x, scatter into g_q/g_k/g_v  (N=2304)
// MODE 1: A = g_y, plain write to out      (N=768)
// ============================================================
#define BM 128
#define BN 128
#define BKK 8

template<int MODE>
__global__ void __launch_bounds__(256) gemm_kernel(
    const float* __restrict__ Ain, const float* __restrict__ W,
    const float* __restrict__ bias, float* __restrict__ out, int N)
{
    __shared__ float As[BKK][BM];
    __shared__ float Bs[BKK][BN];
    const float* A = (MODE == 1) ? g_y : Ain;
    const int bx = blockIdx.x, by = blockIdx.y;
    const int tid = threadIdx.x;
    const int lrow = tid >> 1;            // 0..127
    const int lcol = (tid & 1) * 4;       // 0 or 4
    const float* Ap = A + (size_t)(by * BM + lrow) * K_ + lcol;
    const float* Wp = W + (size_t)(bx * BN + lrow) * K_ + lcol;
    const int tx = tid & 15, ty = tid >> 4;   // 16x16 thread grid

    float acc[8][8];
#pragma unroll
    for (int i = 0; i < 8; i++)
#pragma unroll
        for (int j = 0; j < 8; j++) acc[i][j] = 0.f;

    for (int k0 = 0; k0 < K_; k0 += BKK) {
        float4 a = *(const float4*)(Ap + k0);
        float4 b = *(const float4*)(Wp + k0);
        As[lcol + 0][lrow] = a.x; As[lcol + 1][lrow] = a.y;
        As[lcol + 2][lrow] = a.z; As[lcol + 3][lrow] = a.w;
        Bs[lcol + 0][lrow] = b.x; Bs[lcol + 1][lrow] = b.y;
        Bs[lcol + 2][lrow] = b.z; Bs[lcol + 3][lrow] = b.w;
        __syncthreads();
#pragma unroll
        for (int kk = 0; kk < BKK; kk++) {
            float4 a0 = *(const float4*)&As[kk][ty * 4];
            float4 a1 = *(const float4*)&As[kk][64 + ty * 4];
            float4 b0 = *(const float4*)&Bs[kk][tx * 4];
            float4 b1 = *(const float4*)&Bs[kk][64 + tx * 4];
            float ra[8] = {a0.x, a0.y, a0.z, a0.w, a1.x, a1.y, a1.z, a1.w};
            float rb[8] = {b0.x, b0.y, b0.z, b0.w, b1.x, b1.y, b1.z, b1.w};
#pragma unroll
            for (int i = 0; i < 8; i++)
#pragma unroll
                for (int j = 0; j < 8; j++)
                    acc[i][j] += ra[i] * rb[j];
        }
        __syncthreads();
    }

    // epilogue
#pragma unroll
    for (int i = 0; i < 8; i++) {
        int r = by * BM + ((i < 4) ? (ty * 4 + i) : (64 + ty * 4 + (i - 4)));
#pragma unroll
        for (int j = 0; j < 8; j++) {
            int c = bx * BN + ((j < 4) ? (tx * 4 + j) : (64 + tx * 4 + (j - 4)));
            float v = acc[i][j] + bias[c];
            if (MODE == 0) {
                int which = c / C_;               // 0=q,1=k,2=v
                int cc = c - which * C_;
                int h = cc >> 6, d = cc & 63;     // D=64
                int bi = r >> 10, s = r & 1023;   // S=1024
                float* dst = (which == 0) ? g_q : ((which == 1) ? g_k : g_v);
                dst[(((size_t)(bi * H_ + h)) * S_ + s) * D_ + d] = v;
            } else {
                out[(size_t)r * N + c] = v;
            }
        }
    }
}

// ============================================================
// Flash attention, causal + key mask.
// grid (S/64, H, B), 64 threads; thread t owns query row q0+t.
// q and O-accumulator register-resident (16 float4 each),
// K/V tiles (64x64 f32) staged in smem, broadcast float4 reads.
// Online softmax with chunk-of-16 rescale.
// ============================================================
__global__ void __launch_bounds__(64) attn_kernel(const int* __restrict__ amask)
{
    __shared__ float Ks[64 * 64];
    __shared__ float Vs[64 * 64];
    __shared__ int km[64];

    const int t = threadIdx.x;
    const int h = blockIdx.y, b = blockIdx.z;
    const int q0 = blockIdx.x * 64;
    const int qi = q0 + t;
    const size_t headBase = ((size_t)(b * H_ + h)) * S_;

    const float4* qp = (const float4*)(g_q + (headBase + qi) * D_);
    float4 qreg[16];
#pragma unroll
    for (int r = 0; r < 16; r++) qreg[r] = qp[r];

    float4 acc[16];
#pragma unroll
    for (int r = 0; r < 16; r++) acc[r] = make_float4(0.f, 0.f, 0.f, 0.f);

    float mi = -1e30f, li = 0.f;
    const float scale = 0.125f;   // 1/sqrt(64)

    for (int j0 = 0; j0 <= q0; j0 += 64) {
        const float4* kp = (const float4*)(g_k + (headBase + j0) * D_);
        const float4* vp = (const float4*)(g_v + (headBase + j0) * D_);
#pragma unroll
        for (int r = 0; r < 16; r++) {
            ((float4*)Ks)[r * 64 + t] = kp[r * 64 + t];
            ((float4*)Vs)[r * 64 + t] = vp[r * 64 + t];
        }
        km[t] = amask[b * S_ + j0 + t];
        __syncthreads();

#pragma unroll 1
        for (int jc = 0; jc < 64; jc += 16) {
            float sc[16];
            float cmax = -1e30f;
#pragma unroll
            for (int jj = 0; jj < 16; jj++) {
                const int j = jc + jj;
                const float4* kr = (const float4*)(Ks + j * 64);
                float s0 = 0.f, s1 = 0.f, s2 = 0.f, s3 = 0.f;
#pragma unroll
                for (int r = 0; r < 16; r += 4) {
                    float4 k0v = kr[r], k1v = kr[r + 1], k2v = kr[r + 2], k3v = kr[r + 3];
                    s0 += qreg[r].x * k0v.x + qreg[r].y * k0v.y + qreg[r].z * k0v.z + qreg[r].w * k0v.w;
                    s1 += qreg[r + 1].x * k1v.x + qreg[r + 1].y * k1v.y + qreg[r + 1].z * k1v.z + qreg[r + 1].w * k1v.w;
                    s2 += qreg[r + 2].x * k2v.x + qreg[r + 2].y * k2v.y + qreg[r + 2].z * k2v.z + qreg[r + 2].w * k2v.w;
                    s3 += qreg[r + 3].x * k3v.x + qreg[r + 3].y * k3v.y + qreg[r + 3].z * k3v.z + qreg[r + 3].w * k3v.w;
                }
                float s = ((s0 + s1) + (s2 + s3)) * scale;
                bool ok = ((j0 + j) <= qi) && (km[j] != 0);
                sc[jj] = ok ? s : -1e30f;
                cmax = fmaxf(cmax, sc[jj]);
            }
            float mnew = fmaxf(mi, cmax);
            float corr = __expf(mi - mnew);   // both -1e30 -> exp(0)=1, acc is 0 anyway
            mi = mnew;
            li *= corr;
#pragma unroll
            for (int r = 0; r < 16; r++) {
                acc[r].x *= corr; acc[r].y *= corr;
                acc[r].z *= corr; acc[r].w *= corr;
            }
#pragma unroll
            for (int jj = 0; jj < 16; jj++) {
                float e = (sc[jj] > -1e29f) ? __expf(sc[jj] - mi) : 0.f;
                li += e;
                const float4* vr = (const float4*)(Vs + (jc + jj) * 64);
#pragma unroll
                for (int r = 0; r < 16; r++) {
                    float4 vv = vr[r];
                    acc[r].x += e * vv.x; acc[r].y += e * vv.y;
                    acc[r].z += e * vv.z; acc[r].w += e * vv.w;
                }
            }
        }
        __syncthreads();
    }

    float inv = (li > 0.f) ? (1.f / li) : 0.f;   // fully-masked row -> 0 (matches ref's 2nd masked_fill)
    float4* yp = (float4*)(g_y + ((size_t)(b * S_ + qi)) * C_ + h * D_);
#pragma unroll
    for (int r = 0; r < 16; r++) {
        float4 o;
        o.x = acc[r].x * inv; o.y = acc[r].y * inv;
        o.z = acc[r].z * inv; o.w = acc[r].w * inv;
        yp[r] = o;
    }
}

// ============================================================
extern "C" void kernel_launch(void* const* d_in, const int* in_sizes, int n_in,
                              void* d_out, int out_size)
{
    const float* x      = (const float*)d_in[0];
    const float* w_qkv  = (const float*)d_in[1];
    const float* b_qkv  = (const float*)d_in[2];
    const float* w_out  = (const float*)d_in[3];
    const float* b_out  = (const float*)d_in[4];
    const int*   amask  = (const int*)d_in[5];
    float* out = (float*)d_out;

    // 1) QKV projection, scattered into [B,H,S,D] q/k/v
    gemm_kernel<0><<<dim3((3 * C_) / BN, M_ / BM), 256>>>(x, w_qkv, b_qkv, nullptr, 3 * C_);
    // 2) causal flash attention -> g_y in [B,S,C]
    attn_kernel<<<dim3(S_ / 64, H_, B_), 64>>>(amask);
    // 3) output projection
    gemm_kernel<1><<<dim3(C_ / BN, M_ / BM), 256>>>(nullptr, w_out, b_out, out, C_);
}

// round 13
// speedup vs baseline: 1.7500x; 1.7500x over previous
#include <cuda_runtime.h>
#include <cuda_bf16.h>
#include <stdint.h>
#include <math.h>

#define B_ 8
#define S_ 1024
#define C_ 768
#define H_ 12
#define D_ 64
#define M_ (B_*S_)
#define K_ C_
#define TK 64              // K-chunk: 64 bf16 = 128B row = one SW128 atom
#define KC (K_/TK)         // 12 chunks

// ---------------- scratch (__device__ globals; allocation-free) ----------------
__device__ float g_q[B_*H_*S_*D_];   // [B,H,S,D] fp32
__device__ float g_k[B_*H_*S_*D_];
__device__ float g_v[B_*H_*S_*D_];
__device__ __align__(16) __nv_bfloat16 g_xh[M_*K_],   g_xl[M_*K_];     // x split
__device__ __align__(16) __nv_bfloat16 g_wh[3*C_*K_], g_wl[3*C_*K_];   // w_qkv split
__device__ __align__(16) __nv_bfloat16 g_woh[C_*K_],  g_wol[C_*K_];    // w_out split
__device__ __align__(16) __nv_bfloat16 g_yh[M_*C_],   g_yl[M_*C_];     // attention out split

// ---------------- helpers ----------------
__device__ __forceinline__ uint32_t smem_u32(const void* p) {
    uint32_t a;
    asm("{ .reg .u64 t; cvta.to.shared.u64 t, %1; cvt.u32.u64 %0, t; }" : "=r"(a) : "l"(p));
    return a;
}
__device__ __forceinline__ void ldm_x4(uint32_t* r, uint32_t addr) {
    asm volatile("ldmatrix.sync.aligned.m8n8.x4.shared.b16 {%0,%1,%2,%3}, [%4];"
        : "=r"(r[0]), "=r"(r[1]), "=r"(r[2]), "=r"(r[3]) : "r"(addr));
}
__device__ __forceinline__ void ldm_x2(uint32_t* r, uint32_t addr) {
    asm volatile("ldmatrix.sync.aligned.m8n8.x2.shared.b16 {%0,%1}, [%2];"
        : "=r"(r[0]), "=r"(r[1]) : "r"(addr));
}
__device__ __forceinline__ void mma_bf16(float* c, const uint32_t* a, const uint32_t* b) {
    asm volatile("mma.sync.aligned.m16n8k16.row.col.f32.bf16.bf16.f32 "
        "{%0,%1,%2,%3}, {%4,%5,%6,%7}, {%8,%9}, {%0,%1,%2,%3};"
        : "+f"(c[0]), "+f"(c[1]), "+f"(c[2]), "+f"(c[3])
        : "r"(a[0]), "r"(a[1]), "r"(a[2]), "r"(a[3]), "r"(b[0]), "r"(b[1]));
}
__device__ __forceinline__ void cp_async16(uint32_t dst, const void* src) {
    asm volatile("cp.async.cg.shared.global [%0], [%1], 16;" :: "r"(dst), "l"(src));
}
#define CP_COMMIT() asm volatile("cp.async.commit_group;" ::: "memory")
#define CP_WAIT(n)  asm volatile("cp.async.wait_group %0;" :: "n"(n) : "memory")

// ---------------- fp32 -> (hi, lo) bf16 split converters ----------------
// SEL 0: x -> g_xh/g_xl   1: w_qkv -> g_wh/g_wl   2: w_out -> g_woh/g_wol
template<int SEL>
__global__ void __launch_bounds__(256) cvt_kernel(const float* __restrict__ src, int n4)
{
    __nv_bfloat16* hp = (SEL == 0) ? g_xh : (SEL == 1) ? g_wh : g_woh;
    __nv_bfloat16* lp = (SEL == 0) ? g_xl : (SEL == 1) ? g_wl : g_wol;
    int i = blockIdx.x * 256 + threadIdx.x;
    if (i >= n4) return;
    float4 v = ((const float4*)src)[i];
    __nv_bfloat162 h0, h1, l0, l1;
    h0.x = __float2bfloat16_rn(v.x); h0.y = __float2bfloat16_rn(v.y);
    h1.x = __float2bfloat16_rn(v.z); h1.y = __float2bfloat16_rn(v.w);
    l0.x = __float2bfloat16_rn(v.x - __bfloat162float(h0.x));
    l0.y = __float2bfloat16_rn(v.y - __bfloat162float(h0.y));
    l1.x = __float2bfloat16_rn(v.z - __bfloat162float(h1.x));
    l1.y = __float2bfloat16_rn(v.w - __bfloat162float(h1.y));
    ((__nv_bfloat162*)hp)[i * 2]     = h0;
    ((__nv_bfloat162*)hp)[i * 2 + 1] = h1;
    ((__nv_bfloat162*)lp)[i * 2]     = l0;
    ((__nv_bfloat162*)lp)[i * 2 + 1] = l1;
}

// ============================================================
// mma.sync split-bf16 GEMM: out[m,n] = sum_k A[m,k]*W[n,k] + bias[n]
// CTA 128x128, 256 thr (8 warps, 64x32 warp tiles), TK=64, 2-stage cp.async.
// D += Ah*Wh + Ah*Wl + Al*Wh.
// MODE 0: A=g_xh/l, W=g_wh/l (N=2304), scatter q/k/v.
// MODE 1: A=g_yh/l, W=g_woh/l (N=768), write out.
// ============================================================
#define SMEM_BYTES (2*65536)
// stage s: Ah +0, Al +16384, Wh +32768, Wl +49152 (each 128 rows x 128B, SW128)

template<int MODE>
__global__ void __launch_bounds__(256) gemm_mma(const float* __restrict__ bias,
                                                float* __restrict__ out)
{
    extern __shared__ char smem[];
    const uint32_t sb = smem_u32(smem);
    const int tid = threadIdx.x, lane = tid & 31, wid = tid >> 5;
    const int bx = blockIdx.x, by = blockIdx.y;
    const int wm = wid & 1, wn = wid >> 1;     // warp tile: rows wm*64, cols wn*32
    const int N = (MODE == 0) ? 3 * C_ : C_;

    const __nv_bfloat16* Ah = ((MODE == 0) ? g_xh : g_yh) + (size_t)(by * 128) * K_;
    const __nv_bfloat16* Al = ((MODE == 0) ? g_xl : g_yl) + (size_t)(by * 128) * K_;
    const __nv_bfloat16* Wh = ((MODE == 0) ? g_wh : g_woh) + (size_t)(bx * 128) * K_;
    const __nv_bfloat16* Wl = ((MODE == 0) ? g_wl : g_wol) + (size_t)(bx * 128) * K_;

    float acc[4][4][4];
#pragma unroll
    for (int i = 0; i < 4; i++)
#pragma unroll
        for (int j = 0; j < 4; j++)
#pragma unroll
            for (int l = 0; l < 4; l++) acc[i][j][l] = 0.f;

    // chunk loader: 4 tiles x 1024 16B-units each; 4 units/thread/tile
    // (R12 bug: covered only 512 of 1024 units -> half of each row uninitialized)
    auto load_chunk = [&](int c, int stage) {
        const uint32_t base = sb + stage * 65536;
#pragma unroll
        for (int u = 0; u < 4; u++) {
            const int unit = tid + u * 256;            // 0..1023
            const int row = unit >> 3, c16 = unit & 7; // 128 rows x 8 units
            const uint32_t bo = row * 128 + c16 * 16;
            const uint32_t sw = bo ^ ((bo >> 3) & 0x70);
            const size_t gsrc = (size_t)row * K_ + c * TK + c16 * 8;  // bf16 elems
            cp_async16(base + sw,         Ah + gsrc);
            cp_async16(base + 16384 + sw, Al + gsrc);
            cp_async16(base + 32768 + sw, Wh + gsrc);
            cp_async16(base + 49152 + sw, Wl + gsrc);
        }
    };

    // ldmatrix lane address components
    const int amr = lane & 15, akh = lane >> 4;          // A: row-in-16, k-half
    const int bnr = lane & 7,  bkh = (lane >> 3) & 1;    // B: row-in-8, k-half

    load_chunk(0, 0);
    CP_COMMIT();

    for (int c = 0; c < KC; c++) {
        if (c + 1 < KC) { load_chunk(c + 1, (c + 1) & 1); CP_COMMIT(); CP_WAIT(1); }
        else            { CP_WAIT(0); }
        __syncthreads();

        const uint32_t base = sb + (c & 1) * 65536;
#pragma unroll
        for (int kk = 0; kk < 4; kk++) {
            uint32_t ah[4][4], al_[4][4], bh[4][2], bl[4][2];
#pragma unroll
            for (int mt = 0; mt < 4; mt++) {
                const uint32_t bo = (uint32_t)(wm * 64 + mt * 16 + amr) * 128 + kk * 32 + akh * 16;
                const uint32_t sw = bo ^ ((bo >> 3) & 0x70);
                ldm_x4(ah[mt],  base + sw);
                ldm_x4(al_[mt], base + 16384 + sw);
            }
#pragma unroll
            for (int nt = 0; nt < 4; nt++) {
                const uint32_t bo = (uint32_t)(wn * 32 + nt * 8 + bnr) * 128 + kk * 32 + bkh * 16;
                const uint32_t sw = bo ^ ((bo >> 3) & 0x70);
                ldm_x2(bh[nt], base + 32768 + sw);
                ldm_x2(bl[nt], base + 49152 + sw);
            }
#pragma unroll
            for (int mt = 0; mt < 4; mt++)
#pragma unroll
                for (int nt = 0; nt < 4; nt++) {
                    mma_bf16(acc[mt][nt], ah[mt],  bh[nt]);
                    mma_bf16(acc[mt][nt], ah[mt],  bl[nt]);
                    mma_bf16(acc[mt][nt], al_[mt], bh[nt]);
                }
        }
        __syncthreads();
    }

    // epilogue
    const int gq = lane >> 2, tig = lane & 3;
#pragma unroll
    for (int mt = 0; mt < 4; mt++) {
#pragma unroll
        for (int nt = 0; nt < 4; nt++) {
            const int col = bx * 128 + wn * 32 + nt * 8 + tig * 2;
            const float b0 = bias[col], b1 = bias[col + 1];
#pragma unroll
            for (int h2 = 0; h2 < 2; h2++) {
                const int r = by * 128 + wm * 64 + mt * 16 + gq + h2 * 8;
                float2 v;
                v.x = acc[mt][nt][h2 * 2]     + b0;
                v.y = acc[mt][nt][h2 * 2 + 1] + b1;
                if (MODE == 0) {
                    const int which = col / C_;
                    const int cc = col - which * C_;
                    const int hd = cc >> 6, d = cc & 63;
                    const int bi = r >> 10, srow = r & 1023;
                    float* dst = (which == 0) ? g_q : ((which == 1) ? g_k : g_v);
                    *(float2*)(dst + (((size_t)(bi * H_ + hd)) * S_ + srow) * D_ + d) = v;
                } else {
                    *(float2*)(out + (size_t)r * N + col) = v;
                }
            }
        }
    }
}

// ============================================================
// Flash attention, causal + key mask. Epilogue emits bf16 hi/lo y.
// ============================================================
__global__ void __launch_bounds__(64) attn_kernel(const int* __restrict__ amask)
{
    __shared__ float Ks[64 * 64];
    __shared__ float Vs[64 * 64];
    __shared__ int km[64];

    const int t = threadIdx.x;
    const int h = blockIdx.y, b = blockIdx.z;
    const int q0 = blockIdx.x * 64;
    const int qi = q0 + t;
    const size_t headBase = ((size_t)(b * H_ + h)) * S_;

    const float4* qp = (const float4*)(g_q + (headBase + qi) * D_);
    float4 qreg[16];
#pragma unroll
    for (int r = 0; r < 16; r++) qreg[r] = qp[r];

    float4 acc[16];
#pragma unroll
    for (int r = 0; r < 16; r++) acc[r] = make_float4(0.f, 0.f, 0.f, 0.f);

    float mi = -1e30f, li = 0.f;
    const float scale = 0.125f;

    for (int j0 = 0; j0 <= q0; j0 += 64) {
        const float4* kp = (const float4*)(g_k + (headBase + j0) * D_);
        const float4* vp = (const float4*)(g_v + (headBase + j0) * D_);
#pragma unroll
        for (int r = 0; r < 16; r++) {
            ((float4*)Ks)[r * 64 + t] = kp[r * 64 + t];
            ((float4*)Vs)[r * 64 + t] = vp[r * 64 + t];
        }
        km[t] = amask[b * S_ + j0 + t];
        __syncthreads();

#pragma unroll 1
        for (int jc = 0; jc < 64; jc += 16) {
            float sc[16];
            float cmax = -1e30f;
#pragma unroll
            for (int jj = 0; jj < 16; jj++) {
                const int j = jc + jj;
                const float4* kr = (const float4*)(Ks + j * 64);
                float s0 = 0.f, s1 = 0.f, s2 = 0.f, s3 = 0.f;
#pragma unroll
                for (int r = 0; r < 16; r += 4) {
                    float4 k0v = kr[r], k1v = kr[r + 1], k2v = kr[r + 2], k3v = kr[r + 3];
                    s0 += qreg[r].x * k0v.x + qreg[r].y * k0v.y + qreg[r].z * k0v.z + qreg[r].w * k0v.w;
                    s1 += qreg[r + 1].x * k1v.x + qreg[r + 1].y * k1v.y + qreg[r + 1].z * k1v.z + qreg[r + 1].w * k1v.w;
                    s2 += qreg[r + 2].x * k2v.x + qreg[r + 2].y * k2v.y + qreg[r + 2].z * k2v.z + qreg[r + 2].w * k2v.w;
                    s3 += qreg[r + 3].x * k3v.x + qreg[r + 3].y * k3v.y + qreg[r + 3].z * k3v.z + qreg[r + 3].w * k3v.w;
                }
                float s = ((s0 + s1) + (s2 + s3)) * scale;
                bool ok = ((j0 + j) <= qi) && (km[j] != 0);
                sc[jj] = ok ? s : -1e30f;
                cmax = fmaxf(cmax, sc[jj]);
            }
            float mnew = fmaxf(mi, cmax);
            float corr = __expf(mi - mnew);
            mi = mnew;
            li *= corr;
#pragma unroll
            for (int r = 0; r < 16; r++) {
                acc[r].x *= corr; acc[r].y *= corr;
                acc[r].z *= corr; acc[r].w *= corr;
            }
#pragma unroll
            for (int jj = 0; jj < 16; jj++) {
                float e = (sc[jj] > -1e29f) ? __expf(sc[jj] - mi) : 0.f;
                li += e;
                const float4* vr = (const float4*)(Vs + (jc + jj) * 64);
#pragma unroll
                for (int r = 0; r < 16; r++) {
                    float4 vv = vr[r];
                    acc[r].x += e * vv.x; acc[r].y += e * vv.y;
                    acc[r].z += e * vv.z; acc[r].w += e * vv.w;
                }
            }
        }
        __syncthreads();
    }

    float inv = (li > 0.f) ? (1.f / li) : 0.f;
    const size_t ybase = ((size_t)(b * S_ + qi)) * C_ + h * D_;
#pragma unroll
    for (int r = 0; r < 16; r++) {
        float4 o;
        o.x = acc[r].x * inv; o.y = acc[r].y * inv;
        o.z = acc[r].z * inv; o.w = acc[r].w * inv;
        __nv_bfloat162 h0, h1, l0, l1;
        h0.x = __float2bfloat16_rn(o.x); h0.y = __float2bfloat16_rn(o.y);
        h1.x = __float2bfloat16_rn(o.z); h1.y = __float2bfloat16_rn(o.w);
        l0.x = __float2bfloat16_rn(o.x - __bfloat162float(h0.x));
        l0.y = __float2bfloat16_rn(o.y - __bfloat162float(h0.y));
        l1.x = __float2bfloat16_rn(o.z - __bfloat162float(h1.x));
        l1.y = __float2bfloat16_rn(o.w - __bfloat162float(h1.y));
        ((__nv_bfloat162*)(g_yh + ybase + r * 4))[0] = h0;
        ((__nv_bfloat162*)(g_yh + ybase + r * 4))[1] = h1;
        ((__nv_bfloat162*)(g_yl + ybase + r * 4))[0] = l0;
        ((__nv_bfloat162*)(g_yl + ybase + r * 4))[1] = l1;
    }
}

// ============================================================
extern "C" void kernel_launch(void* const* d_in, const int* in_sizes, int n_in,
                              void* d_out, int out_size)
{
    const float* x      = (const float*)d_in[0];
    const float* w_qkv  = (const float*)d_in[1];
    const float* b_qkv  = (const float*)d_in[2];
    const float* w_out  = (const float*)d_in[3];
    const float* b_out  = (const float*)d_in[4];
    const int*   amask  = (const int*)d_in[5];
    float* out = (float*)d_out;

    cudaFuncSetAttribute(gemm_mma<0>, cudaFuncAttributeMaxDynamicSharedMemorySize, SMEM_BYTES);
    cudaFuncSetAttribute(gemm_mma<1>, cudaFuncAttributeMaxDynamicSharedMemorySize, SMEM_BYTES);

    // 0) split-precision conversions (bf16 hi/lo)
    cvt_kernel<0><<<(M_ * K_ / 4 + 255) / 256, 256>>>(x, M_ * K_ / 4);
    cvt_kernel<1><<<(3 * C_ * K_ / 4 + 255) / 256, 256>>>(w_qkv, 3 * C_ * K_ / 4);
    cvt_kernel<2><<<(C_ * K_ / 4 + 255) / 256, 256>>>(w_out, C_ * K_ / 4);

    // 1) QKV projection (HMMA split-bf16), scattered into [B,H,S,D] q/k/v
    gemm_mma<0><<<dim3((3 * C_) / 128, M_ / 128), 256, SMEM_BYTES>>>(b_qkv, nullptr);
    // 2) causal flash attention -> g_yh/g_yl (bf16 hi/lo, [B,S,C])
    attn_kernel<<<dim3(S_ / 64, H_, B_), 64>>>(amask);
    // 3) output projection (HMMA split-bf16)
    gemm_mma<1><<<dim3(C_ / 128, M_ / 128), 256, SMEM_BYTES>>>(b_out, out);
}

// round 14
// speedup vs baseline: 2.6768x; 1.5296x over previous
#include <cuda_runtime.h>
#include <cuda_bf16.h>
#include <stdint.h>
#include <math.h>

#define B_ 8
#define S_ 1024
#define C_ 768
#define H_ 12
#define D_ 64
#define M_ (B_*S_)
#define K_ C_
#define TK 64              // K-chunk: 64 bf16 = 128B row
#define KC (K_/TK)         // 12 chunks

// ---------------- scratch (__device__ globals; allocation-free) ----------------
__device__ __align__(16) __nv_bfloat16 g_xh[M_*K_],   g_xl[M_*K_];     // x split
__device__ __align__(16) __nv_bfloat16 g_wh[3*C_*K_], g_wl[3*C_*K_];   // w_qkv split
__device__ __align__(16) __nv_bfloat16 g_woh[C_*K_],  g_wol[C_*K_];    // w_out split
__device__ __align__(16) __nv_bfloat16 g_qh[B_*H_*S_*D_], g_ql[B_*H_*S_*D_];  // q/8 [B,H,S,D]
__device__ __align__(16) __nv_bfloat16 g_kh[B_*H_*S_*D_], g_kl[B_*H_*S_*D_];  // k   [B,H,S,D]
__device__ __align__(16) __nv_bfloat16 g_vth[B_*H_*D_*S_], g_vtl[B_*H_*D_*S_];// v^T [B,H,D,S]
__device__ __align__(16) __nv_bfloat16 g_yh[M_*C_],   g_yl[M_*C_];     // attn out [B,S,C]

// ---------------- helpers ----------------
__device__ __forceinline__ uint32_t smem_u32(const void* p) {
    uint32_t a;
    asm("{ .reg .u64 t; cvta.to.shared.u64 t, %1; cvt.u32.u64 %0, t; }" : "=r"(a) : "l"(p));
    return a;
}
__device__ __forceinline__ void ldm_x4(uint32_t* r, uint32_t addr) {
    asm volatile("ldmatrix.sync.aligned.m8n8.x4.shared.b16 {%0,%1,%2,%3}, [%4];"
        : "=r"(r[0]), "=r"(r[1]), "=r"(r[2]), "=r"(r[3]) : "r"(addr));
}
__device__ __forceinline__ void ldm_x2(uint32_t* r, uint32_t addr) {
    asm volatile("ldmatrix.sync.aligned.m8n8.x2.shared.b16 {%0,%1}, [%2];"
        : "=r"(r[0]), "=r"(r[1]) : "r"(addr));
}
__device__ __forceinline__ void mma_bf16(float* c, const uint32_t* a, const uint32_t* b) {
    asm volatile("mma.sync.aligned.m16n8k16.row.col.f32.bf16.bf16.f32 "
        "{%0,%1,%2,%3}, {%4,%5,%6,%7}, {%8,%9}, {%0,%1,%2,%3};"
        : "+f"(c[0]), "+f"(c[1]), "+f"(c[2]), "+f"(c[3])
        : "r"(a[0]), "r"(a[1]), "r"(a[2]), "r"(a[3]), "r"(b[0]), "r"(b[1]));
}
__device__ __forceinline__ void cp_async16(uint32_t dst, const void* src) {
    asm volatile("cp.async.cg.shared.global [%0], [%1], 16;" :: "r"(dst), "l"(src));
}
#define CP_COMMIT() asm volatile("cp.async.commit_group;" ::: "memory")
#define CP_WAIT(n)  asm volatile("cp.async.wait_group %0;" :: "n"(n) : "memory")

__device__ __forceinline__ uint32_t pack_bf2(float x, float y) {
    __nv_bfloat162 t;
    t.x = __float2bfloat16_rn(x); t.y = __float2bfloat16_rn(y);
    return *(uint32_t*)&t;
}
__device__ __forceinline__ void split_bf2(float x, float y,
                                          __nv_bfloat162& h, __nv_bfloat162& l) {
    h.x = __float2bfloat16_rn(x); h.y = __float2bfloat16_rn(y);
    l.x = __float2bfloat16_rn(x - __bfloat162float(h.x));
    l.y = __float2bfloat16_rn(y - __bfloat162float(h.y));
}

// ---------------- fp32 -> (hi, lo) bf16 split converters ----------------
template<int SEL>
__global__ void __launch_bounds__(256) cvt_kernel(const float* __restrict__ src, int n4)
{
    __nv_bfloat16* hp = (SEL == 0) ? g_xh : (SEL == 1) ? g_wh : g_woh;
    __nv_bfloat16* lp = (SEL == 0) ? g_xl : (SEL == 1) ? g_wl : g_wol;
    int i = blockIdx.x * 256 + threadIdx.x;
    if (i >= n4) return;
    float4 v = ((const float4*)src)[i];
    __nv_bfloat162 h0, h1, l0, l1;
    split_bf2(v.x, v.y, h0, l0);
    split_bf2(v.z, v.w, h1, l1);
    ((__nv_bfloat162*)hp)[i * 2]     = h0;
    ((__nv_bfloat162*)hp)[i * 2 + 1] = h1;
    ((__nv_bfloat162*)lp)[i * 2]     = l0;
    ((__nv_bfloat162*)lp)[i * 2 + 1] = l1;
}

// ============================================================
// mma.sync split-bf16 GEMM (CTA 128x128, 8 warps, TK=64, 2-stage).
// MODE 0: x @ w_qkv^T -> q/8, k (bf16 hi/lo [B,H,S,D]); v^T (bf16 hi/lo [B,H,D,S])
// MODE 1: y @ w_out^T -> out (fp32)
// ============================================================
#define SMEM_BYTES (2*65536)

template<int MODE>
__global__ void __launch_bounds__(256) gemm_mma(const float* __restrict__ bias,
                                                float* __restrict__ out)
{
    extern __shared__ char smem[];
    const uint32_t sb = smem_u32(smem);
    const int tid = threadIdx.x, lane = tid & 31, wid = tid >> 5;
    const int bx = blockIdx.x, by = blockIdx.y;
    const int wm = wid & 1, wn = wid >> 1;
    const int N = (MODE == 0) ? 3 * C_ : C_;

    const __nv_bfloat16* Ah = ((MODE == 0) ? g_xh : g_yh) + (size_t)(by * 128) * K_;
    const __nv_bfloat16* Al = ((MODE == 0) ? g_xl : g_yl) + (size_t)(by * 128) * K_;
    const __nv_bfloat16* Wh = ((MODE == 0) ? g_wh : g_woh) + (size_t)(bx * 128) * K_;
    const __nv_bfloat16* Wl = ((MODE == 0) ? g_wl : g_wol) + (size_t)(bx * 128) * K_;

    float acc[4][4][4];
#pragma unroll
    for (int i = 0; i < 4; i++)
#pragma unroll
        for (int j = 0; j < 4; j++)
#pragma unroll
            for (int l = 0; l < 4; l++) acc[i][j][l] = 0.f;

    auto load_chunk = [&](int c, int stage) {
        const uint32_t base = sb + stage * 65536;
#pragma unroll
        for (int u = 0; u < 4; u++) {
            const int unit = tid + u * 256;
            const int row = unit >> 3, c16 = unit & 7;
            const uint32_t bo = row * 128 + c16 * 16;
            const uint32_t sw = bo ^ ((bo >> 3) & 0x70);
            const size_t gsrc = (size_t)row * K_ + c * TK + c16 * 8;
            cp_async16(base + sw,         Ah + gsrc);
            cp_async16(base + 16384 + sw, Al + gsrc);
            cp_async16(base + 32768 + sw, Wh + gsrc);
            cp_async16(base + 49152 + sw, Wl + gsrc);
        }
    };

    const int amr = lane & 15, akh = lane >> 4;
    const int bnr = lane & 7,  bkh = (lane >> 3) & 1;

    load_chunk(0, 0);
    CP_COMMIT();

    for (int c = 0; c < KC; c++) {
        if (c + 1 < KC) { load_chunk(c + 1, (c + 1) & 1); CP_COMMIT(); CP_WAIT(1); }
        else            { CP_WAIT(0); }
        __syncthreads();

        const uint32_t base = sb + (c & 1) * 65536;
#pragma unroll
        for (int kk = 0; kk < 4; kk++) {
            uint32_t ah[4][4], al_[4][4], bh[4][2], bl[4][2];
#pragma unroll
            for (int mt = 0; mt < 4; mt++) {
                const uint32_t bo = (uint32_t)(wm * 64 + mt * 16 + amr) * 128 + kk * 32 + akh * 16;
                const uint32_t sw = bo ^ ((bo >> 3) & 0x70);
                ldm_x4(ah[mt],  base + sw);
                ldm_x4(al_[mt], base + 16384 + sw);
            }
#pragma unroll
            for (int nt = 0; nt < 4; nt++) {
                const uint32_t bo = (uint32_t)(wn * 32 + nt * 8 + bnr) * 128 + kk * 32 + bkh * 16;
                const uint32_t sw = bo ^ ((bo >> 3) & 0x70);
                ldm_x2(bh[nt], base + 32768 + sw);
                ldm_x2(bl[nt], base + 49152 + sw);
            }
#pragma unroll
            for (int mt = 0; mt < 4; mt++)
#pragma unroll
                for (int nt = 0; nt < 4; nt++) {
                    mma_bf16(acc[mt][nt], ah[mt],  bh[nt]);
                    mma_bf16(acc[mt][nt], ah[mt],  bl[nt]);
                    mma_bf16(acc[mt][nt], al_[mt], bh[nt]);
                }
        }
        __syncthreads();
    }

    // epilogue
    const int gq = lane >> 2, tig = lane & 3;
#pragma unroll
    for (int mt = 0; mt < 4; mt++) {
#pragma unroll
        for (int nt = 0; nt < 4; nt++) {
            const int col = bx * 128 + wn * 32 + nt * 8 + tig * 2;
            const float b0 = bias[col], b1 = bias[col + 1];
#pragma unroll
            for (int h2 = 0; h2 < 2; h2++) {
                const int r = by * 128 + wm * 64 + mt * 16 + gq + h2 * 8;
                float vx = acc[mt][nt][h2 * 2]     + b0;
                float vy = acc[mt][nt][h2 * 2 + 1] + b1;
                if (MODE == 0) {
                    const int which = col / C_;
                    const int cc = col - which * C_;
                    const int hd = cc >> 6, d = cc & 63;
                    const int bi = r >> 10, srow = r & 1023;
                    const size_t hb = (size_t)(bi * H_ + hd);
                    __nv_bfloat162 hh, ll;
                    if (which == 0) {           // q: pre-scale by 1/sqrt(D)=1/8
                        split_bf2(vx * 0.125f, vy * 0.125f, hh, ll);
                        *(__nv_bfloat162*)(g_qh + (hb * S_ + srow) * D_ + d) = hh;
                        *(__nv_bfloat162*)(g_ql + (hb * S_ + srow) * D_ + d) = ll;
                    } else if (which == 1) {    // k
                        split_bf2(vx, vy, hh, ll);
                        *(__nv_bfloat162*)(g_kh + (hb * S_ + srow) * D_ + d) = hh;
                        *(__nv_bfloat162*)(g_kl + (hb * S_ + srow) * D_ + d) = ll;
                    } else {                    // v: transposed [B,H,D,S]
                        split_bf2(vx, vy, hh, ll);
                        g_vth[(hb * D_ + d)     * S_ + srow] = hh.x;
                        g_vtl[(hb * D_ + d)     * S_ + srow] = ll.x;
                        g_vth[(hb * D_ + d + 1) * S_ + srow] = hh.y;
                        g_vtl[(hb * D_ + d + 1) * S_ + srow] = ll.y;
                    }
                } else {
                    *(float2*)(out + (size_t)r * N + col) = make_float2(vx, vy);
                }
            }
        }
    }
}

// ============================================================
// Tensor-core flash attention (causal + key mask).
// CTA: 64 q-rows x 1 head, 128 threads (4 warps x 16 rows).
// kv tiles of 64, double-buffered cp.async (K hi/lo + V^T hi/lo + mask).
// S = Qh*Kh + Qh*Kl + Ql*Kh (q pre-scaled); online softmax in fragments;
// P repacked C->A in regs; O += Ph*Vh + Ph*Vl + Pl*Vh. Emits y bf16 hi/lo.
// ============================================================
// smem: Qh 0, Ql 8192, stages at 16384 (stride 32768: Kh+0 Kl+8192 Vh+16384 Vl+24576),
// mask ints at 81920 (stride 256). total 82432.
#define ATTN_SMEM 82432

__global__ void __launch_bounds__(128) attn_mma(const int* __restrict__ amask)
{
    extern __shared__ char smem[];
    const uint32_t sb = smem_u32(smem);
    const int tid = threadIdx.x, lane = tid & 31, wq = tid >> 5;
    const int h = blockIdx.y, b = blockIdx.z;
    const int q0 = blockIdx.x * 64;
    const size_t hb = (size_t)(b * H_ + h);

    const __nv_bfloat16* Qhp = g_qh + (hb * S_ + q0) * D_;
    const __nv_bfloat16* Qlp = g_ql + (hb * S_ + q0) * D_;
    const __nv_bfloat16* Khp = g_kh + hb * S_ * D_;
    const __nv_bfloat16* Klp = g_kl + hb * S_ * D_;
    const __nv_bfloat16* Vhp = g_vth + hb * D_ * S_;
    const __nv_bfloat16* Vlp = g_vtl + hb * D_ * S_;
    const int* am = amask + b * S_;

    const uint32_t OQH = 0, OQL = 8192, OST = 16384, SSTR = 32768, OMB = 81920;
    const int amr = lane & 15, akh = lane >> 4;
    const int bnr = lane & 7,  bkh = (lane >> 3) & 1;
    const int gq = lane >> 2,  tig = lane & 3;
    const int rlo = wq * 16 + gq;          // local q row (low half)

    // ---- prologue: Q tiles ----
#pragma unroll
    for (int u = 0; u < 4; u++) {
        const int unit = tid + u * 128;          // 0..511
        const int row = unit >> 3, c16 = unit & 7;
        const uint32_t bo = row * 128 + c16 * 16;
        const uint32_t sw = bo ^ ((bo >> 3) & 0x70);
        const size_t gsrc = (size_t)row * D_ + c16 * 8;
        cp_async16(sb + OQH + sw, Qhp + gsrc);
        cp_async16(sb + OQL + sw, Qlp + gsrc);
    }
    CP_COMMIT();

    auto load_stage = [&](int j0, int st) {
        const uint32_t base = sb + OST + st * SSTR;
#pragma unroll
        for (int u = 0; u < 4; u++) {
            const int unit = tid + u * 128;
            const int row = unit >> 3, c16 = unit & 7;
            const uint32_t bo = row * 128 + c16 * 16;
            const uint32_t sw = bo ^ ((bo >> 3) & 0x70);
            cp_async16(base + sw,         Khp + (size_t)(j0 + row) * D_ + c16 * 8);
            cp_async16(base + 8192 + sw,  Klp + (size_t)(j0 + row) * D_ + c16 * 8);
            cp_async16(base + 16384 + sw, Vhp + (size_t)row * S_ + j0 + c16 * 8);
            cp_async16(base + 24576 + sw, Vlp + (size_t)row * S_ + j0 + c16 * 8);
        }
        if (tid < 16) cp_async16(sb + OMB + st * 256 + tid * 16, am + j0 + tid * 4);
    };

    load_stage(0, 0);
    CP_COMMIT();
    CP_WAIT(1);              // Q group done (stage0 may still be in flight)
    __syncthreads();

    // Q fragments -> registers
    uint32_t qfh[4][4], qfl[4][4];
#pragma unroll
    for (int kk = 0; kk < 4; kk++) {
        const uint32_t bo = (uint32_t)(wq * 16 + amr) * 128 + kk * 32 + akh * 16;
        const uint32_t sw = bo ^ ((bo >> 3) & 0x70);
        ldm_x4(qfh[kk], sb + OQH + sw);
        ldm_x4(qfl[kk], sb + OQL + sw);
    }

    float o[8][4];
#pragma unroll
    for (int i = 0; i < 8; i++)
#pragma unroll
        for (int j = 0; j < 4; j++) o[i][j] = 0.f;
    float m0 = -1e28f, m1 = -1e28f, l0 = 0.f, l1 = 0.f;

    const int ntiles = q0 / 64 + 1;
    for (int it = 0; it < ntiles; it++) {
        if (it + 1 < ntiles) { load_stage((it + 1) * 64, (it + 1) & 1); CP_COMMIT(); CP_WAIT(1); }
        else                 { CP_WAIT(0); }
        __syncthreads();

        const int st = it & 1;
        const uint32_t base = sb + OST + st * SSTR;
        const bool diag = (it == ntiles - 1);

        // ---- S = Q K^T (split) ----
        float s[8][4];
#pragma unroll
        for (int i = 0; i < 8; i++)
#pragma unroll
            for (int j = 0; j < 4; j++) s[i][j] = 0.f;
#pragma unroll
        for (int kk = 0; kk < 4; kk++)
#pragma unroll
            for (int nt = 0; nt < 8; nt++) {
                const uint32_t bo = (uint32_t)(nt * 8 + bnr) * 128 + kk * 32 + bkh * 16;
                const uint32_t sw = bo ^ ((bo >> 3) & 0x70);
                uint32_t kh2[2], kl2[2];
                ldm_x2(kh2, base + sw);
                ldm_x2(kl2, base + 8192 + sw);
                mma_bf16(s[nt], qfh[kk], kh2);
                mma_bf16(s[nt], qfh[kk], kl2);
                mma_bf16(s[nt], qfl[kk], kh2);
            }

        // ---- mask ----
        const int* kmt = (const int*)(smem + OMB + st * 256);
#pragma unroll
        for (int nt = 0; nt < 8; nt++) {
            const int c0 = nt * 8 + tig * 2;
            const int k0 = kmt[c0], k1 = kmt[c0 + 1];
            bool v00 = k0 && (!diag || c0     <= rlo);
            bool v10 = k1 && (!diag || c0 + 1 <= rlo);
            bool v01 = k0 && (!diag || c0     <= rlo + 8);
            bool v11 = k1 && (!diag || c0 + 1 <= rlo + 8);
            if (!v00) s[nt][0] = -1e30f;
            if (!v10) s[nt][1] = -1e30f;
            if (!v01) s[nt][2] = -1e30f;
            if (!v11) s[nt][3] = -1e30f;
        }

        // ---- online softmax ----
        float mt0 = -1e30f, mt1 = -1e30f;
#pragma unroll
        for (int nt = 0; nt < 8; nt++) {
            mt0 = fmaxf(mt0, fmaxf(s[nt][0], s[nt][1]));
            mt1 = fmaxf(mt1, fmaxf(s[nt][2], s[nt][3]));
        }
        mt0 = fmaxf(mt0, __shfl_xor_sync(0xffffffffu, mt0, 1));
        mt0 = fmaxf(mt0, __shfl_xor_sync(0xffffffffu, mt0, 2));
        mt1 = fmaxf(mt1, __shfl_xor_sync(0xffffffffu, mt1, 1));
        mt1 = fmaxf(mt1, __shfl_xor_sync(0xffffffffu, mt1, 2));
        const float mn0 = fmaxf(m0, mt0), mn1 = fmaxf(m1, mt1);
        const float cr0 = __expf(m0 - mn0), cr1 = __expf(m1 - mn1);
        m0 = mn0; m1 = mn1;
        l0 *= cr0; l1 *= cr1;
#pragma unroll
        for (int nt = 0; nt < 8; nt++) {
            o[nt][0] *= cr0; o[nt][1] *= cr0;
            o[nt][2] *= cr1; o[nt][3] *= cr1;
        }

        uint32_t pah[4][4], pal[4][4];
        float rs0 = 0.f, rs1 = 0.f;
#pragma unroll
        for (int nt = 0; nt < 8; nt++) {
            float p0 = __expf(s[nt][0] - m0);
            float p1 = __expf(s[nt][1] - m0);
            float p2 = __expf(s[nt][2] - m1);
            float p3 = __expf(s[nt][3] - m1);
            rs0 += p0 + p1; rs1 += p2 + p3;
            __nv_bfloat162 h01, l01, h23, l23;
            split_bf2(p0, p1, h01, l01);
            split_bf2(p2, p3, h23, l23);
            const int ks = nt >> 1, hf = nt & 1;
            pah[ks][hf * 2]     = *(uint32_t*)&h01;
            pah[ks][hf * 2 + 1] = *(uint32_t*)&h23;
            pal[ks][hf * 2]     = *(uint32_t*)&l01;
            pal[ks][hf * 2 + 1] = *(uint32_t*)&l23;
        }
        rs0 += __shfl_xor_sync(0xffffffffu, rs0, 1);
        rs0 += __shfl_xor_sync(0xffffffffu, rs0, 2);
        rs1 += __shfl_xor_sync(0xffffffffu, rs1, 1);
        rs1 += __shfl_xor_sync(0xffffffffu, rs1, 2);
        l0 += rs0; l1 += rs1;

        // ---- O += P V (split) ----
#pragma unroll
        for (int ks = 0; ks < 4; ks++)
#pragma unroll
            for (int ntd = 0; ntd < 8; ntd++) {
                const uint32_t bo = (uint32_t)(ntd * 8 + bnr) * 128 + ks * 32 + bkh * 16;
                const uint32_t sw = bo ^ ((bo >> 3) & 0x70);
                uint32_t vh2[2], vl2[2];
                ldm_x2(vh2, base + 16384 + sw);
                ldm_x2(vl2, base + 24576 + sw);
                mma_bf16(o[ntd], pah[ks], vh2);
                mma_bf16(o[ntd], pah[ks], vl2);
                mma_bf16(o[ntd], pal[ks], vh2);
            }
        __syncthreads();
    }

    // ---- output: y bf16 hi/lo, [B,S,C] ----
    const float inv0 = (l0 > 0.f) ? (1.f / l0) : 0.f;
    const float inv1 = (l1 > 0.f) ? (1.f / l1) : 0.f;
    const size_t yr0 = ((size_t)(b * S_) + q0 + rlo)     * C_ + h * D_;
    const size_t yr1 = ((size_t)(b * S_) + q0 + rlo + 8) * C_ + h * D_;
#pragma unroll
    for (int nt = 0; nt < 8; nt++) {
        const int d = nt * 8 + tig * 2;
        __nv_bfloat162 hh, ll;
        split_bf2(o[nt][0] * inv0, o[nt][1] * inv0, hh, ll);
        *(__nv_bfloat162*)(g_yh + yr0 + d) = hh;
        *(__nv_bfloat162*)(g_yl + yr0 + d) = ll;
        split_bf2(o[nt][2] * inv1, o[nt][3] * inv1, hh, ll);
        *(__nv_bfloat162*)(g_yh + yr1 + d) = hh;
        *(__nv_bfloat162*)(g_yl + yr1 + d) = ll;
    }
}

// ============================================================
extern "C" void kernel_launch(void* const* d_in, const int* in_sizes, int n_in,
                              void* d_out, int out_size)
{
    const float* x      = (const float*)d_in[0];
    const float* w_qkv  = (const float*)d_in[1];
    const float* b_qkv  = (const float*)d_in[2];
    const float* w_out  = (const float*)d_in[3];
    const float* b_out  = (const float*)d_in[4];
    const int*   amask  = (const int*)d_in[5];
    float* out = (float*)d_out;

    cudaFuncSetAttribute(gemm_mma<0>, cudaFuncAttributeMaxDynamicSharedMemorySize, SMEM_BYTES);
    cudaFuncSetAttribute(gemm_mma<1>, cudaFuncAttributeMaxDynamicSharedMemorySize, SMEM_BYTES);
    cudaFuncSetAttribute(attn_mma,    cudaFuncAttributeMaxDynamicSharedMemorySize, ATTN_SMEM);

    // 0) split-precision conversions
    cvt_kernel<0><<<(M_ * K_ / 4 + 255) / 256, 256>>>(x, M_ * K_ / 4);
    cvt_kernel<1><<<(3 * C_ * K_ / 4 + 255) / 256, 256>>>(w_qkv, 3 * C_ * K_ / 4);
    cvt_kernel<2><<<(C_ * K_ / 4 + 255) / 256, 256>>>(w_out, C_ * K_ / 4);

    // 1) QKV projection -> q/8, k [B,H,S,D], v^T [B,H,D,S] (all bf16 hi/lo)
    gemm_mma<0><<<dim3((3 * C_) / 128, M_ / 128), 256, SMEM_BYTES>>>(b_qkv, nullptr);
    // 2) tensor-core causal flash attention -> g_yh/g_yl
    attn_mma<<<dim3(S_ / 64, H_, B_), 128, ATTN_SMEM>>>(amask);
    // 3) output projection
    gemm_mma<1><<<dim3(C_ / 128, M_ / 128), 256, SMEM_BYTES>>>(b_out, out);
}